// round 13
// baseline (speedup 1.0000x reference)
#include <cuda_runtime.h>
#include <cuda_bf16.h>
#include <cuda_fp8.h>
#include <cstdint>

// NT-Xent loss, N=4096, D=256, T=0.5 — FP8 (e4m3) mma.sync m16n8k32 version.
// sim = cos/T in [-2,2] => lse = 2 + log(sum exp(sim-2)) : stable, no max pass.
// Grid 128 = 64 row-bands(128 rows) x 2 column halves(4096 cols).
// Per CTA: A band [128x256] fp8 smem-resident; 32 B tiles, 3-buffer cp.async
// pipeline with ONE barrier per tile; warp grid 4x4, warp tile m32 x n32.

#define TWO_N 8192
#define HALF_N 4096
#define DD 256
#define BM 128
#define BN 128
#define NT 32                 // tiles per CTA (4096 / BN)
#define SBB 272               // smem row stride bytes (256 + 16 pad -> 4-bank shift/row)
#define NTHREADS 512

__device__ uint8_t g_zn8[TWO_N * DD];     // normalized rows, e4m3 (2 MB, L2-resident)
__device__ float g_p[2 * TWO_N];
__device__ float g_t[2 * TWO_N];

#define TILE_BYTES (BM * SBB)                  // 34816
#define SMEM_BYTES (4 * TILE_BYTES)            // A + 3 B buffers = 139264

// ---------------- PTX helpers ----------------
__device__ __forceinline__ void cp16(uint32_t dst, const void* src) {
    asm volatile("cp.async.cg.shared.global [%0], [%1], 16;" :: "r"(dst), "l"(src));
}
__device__ __forceinline__ void cp_commit() { asm volatile("cp.async.commit_group;"); }
template <int N> __device__ __forceinline__ void cp_wait() {
    asm volatile("cp.async.wait_group %0;" :: "n"(N));
}
__device__ __forceinline__ void ldsm4(uint32_t& x0, uint32_t& x1, uint32_t& x2, uint32_t& x3,
                                      uint32_t addr) {
    asm volatile("ldmatrix.sync.aligned.m8n8.x4.shared.b16 {%0,%1,%2,%3}, [%4];"
                 : "=r"(x0), "=r"(x1), "=r"(x2), "=r"(x3) : "r"(addr));
}
__device__ __forceinline__ void mma16832(float* c, const uint32_t* a, uint32_t b0, uint32_t b1) {
    asm volatile("mma.sync.aligned.m16n8k32.row.col.f32.e4m3.e4m3.f32 "
                 "{%0,%1,%2,%3}, {%4,%5,%6,%7}, {%8,%9}, {%0,%1,%2,%3};"
                 : "+f"(c[0]), "+f"(c[1]), "+f"(c[2]), "+f"(c[3])
                 : "r"(a[0]), "r"(a[1]), "r"(a[2]), "r"(a[3]), "r"(b0), "r"(b1));
}

// ---------------- phase 1: normalize fp32 -> e4m3 (warp per row) ----------------
__global__ void normalize_kernel(const float* __restrict__ z1,
                                 const float* __restrict__ z2) {
    int w = threadIdx.x >> 5, lane = threadIdx.x & 31;
    int row = blockIdx.x * 8 + w;
    const float* src = (row < HALF_N) ? (z1 + (size_t)row * DD)
                                      : (z2 + (size_t)(row - HALF_N) * DD);
    float4 f0 = *(const float4*)(src + lane * 8);
    float4 f1 = *(const float4*)(src + lane * 8 + 4);
    float ss = f0.x * f0.x + f0.y * f0.y + f0.z * f0.z + f0.w * f0.w
             + f1.x * f1.x + f1.y * f1.y + f1.z * f1.z + f1.w * f1.w;
#pragma unroll
    for (int o = 16; o > 0; o >>= 1) ss += __shfl_xor_sync(0xffffffffu, ss, o);
    float inv = 1.0f / fmaxf(sqrtf(ss), 1e-8f);

    uint8_t ob[8];
    ob[0] = (uint8_t)__nv_cvt_float_to_fp8(f0.x * inv, __NV_SATFINITE, __NV_E4M3);
    ob[1] = (uint8_t)__nv_cvt_float_to_fp8(f0.y * inv, __NV_SATFINITE, __NV_E4M3);
    ob[2] = (uint8_t)__nv_cvt_float_to_fp8(f0.z * inv, __NV_SATFINITE, __NV_E4M3);
    ob[3] = (uint8_t)__nv_cvt_float_to_fp8(f0.w * inv, __NV_SATFINITE, __NV_E4M3);
    ob[4] = (uint8_t)__nv_cvt_float_to_fp8(f1.x * inv, __NV_SATFINITE, __NV_E4M3);
    ob[5] = (uint8_t)__nv_cvt_float_to_fp8(f1.y * inv, __NV_SATFINITE, __NV_E4M3);
    ob[6] = (uint8_t)__nv_cvt_float_to_fp8(f1.z * inv, __NV_SATFINITE, __NV_E4M3);
    ob[7] = (uint8_t)__nv_cvt_float_to_fp8(f1.w * inv, __NV_SATFINITE, __NV_E4M3);
    *(uint2*)(g_zn8 + (size_t)row * DD + lane * 8) = *(const uint2*)ob;
}

// ---------------- phase 2: FP8 HMMA sweep + online exp-sum ----------------
__global__ __launch_bounds__(NTHREADS, 1) void ntxent_mma_kernel() {
    extern __shared__ __align__(16) char smem[];

    const int tid = threadIdx.x;
    const int lane = tid & 31, wid = tid >> 5;
    const int warp_m = wid & 3;    // 0..3 -> 32-row slice
    const int warp_n = wid >> 2;   // 0..3 -> 32-col slice
    const int band = blockIdx.x >> 1;
    const int ch = blockIdx.x & 1;
    const int row0 = band * BM;
    const int colbase = ch * (NT * BN);   // 0 or 4096

    const uint32_t As_u = (uint32_t)__cvta_generic_to_shared(smem);
    const uint32_t Bu[3] = { As_u + TILE_BYTES, As_u + 2 * TILE_BYTES, As_u + 3 * TILE_BYTES };

    // --- prologue: group0 = A band + B tile0; group1 = B tile1 ---
#pragma unroll
    for (int q = 0; q < 4; q++) {          // 128 rows x 16 chunks = 2048 chunks each
        int c = tid + q * NTHREADS;
        int row = c >> 4, off = c & 15;
        cp16(As_u + row * SBB + off * 16, g_zn8 + (size_t)(row0 + row) * DD + off * 16);
        cp16(Bu[0] + row * SBB + off * 16, g_zn8 + (size_t)(colbase + row) * DD + off * 16);
    }
    cp_commit();
#pragma unroll
    for (int q = 0; q < 4; q++) {
        int c = tid + q * NTHREADS;
        int row = c >> 4, off = c & 15;
        cp16(Bu[1] + row * SBB + off * 16, g_zn8 + (size_t)(colbase + BN + row) * DD + off * 16);
    }
    cp_commit();

    // --- ldmatrix per-lane addressing (byte-isomorphic to validated bf16 layout) ---
    const int g = lane >> 3, rr = lane & 7;
    const uint32_t a_off0 = (uint32_t)((warp_m * 32 + (lane & 15)) * SBB + (lane >> 4) * 16);
    const uint32_t a_off1 = a_off0 + 16 * SBB;
    const uint32_t b_off0 = (uint32_t)((warp_n * 32 + (g >> 1) * 8 + rr) * SBB + (g & 1) * 16);
    const uint32_t b_off1 = b_off0 + 16 * SBB;

    const int gid = lane >> 2, qd = lane & 3;

    float p[2][2]  = {{0.f, 0.f}, {0.f, 0.f}};
    float tv[2][2] = {{0.f, 0.f}, {0.f, 0.f}};

    for (int it = 0; it < NT; it++) {
        // pending groups: {it, it+1}; wait until tile it's group is complete
        cp_wait<1>();
        __syncthreads();   // all threads have tile it resident; all done reading tile it-1

        // prefetch tile it+2 into buf[(it+2)%3] (read for tile it-1 finished above)
        if (it + 2 < NT) {
            const int cn = colbase + (it + 2) * BN;
            const uint32_t Bp = Bu[(it + 2) % 3];
#pragma unroll
            for (int q = 0; q < 4; q++) {
                int c = tid + q * NTHREADS;
                int row = c >> 4, off = c & 15;
                cp16(Bp + row * SBB + off * 16, g_zn8 + (size_t)(cn + row) * DD + off * 16);
            }
        }
        cp_commit();       // empty groups at tail keep wait accounting consistent

        const uint32_t Bc = Bu[it % 3];
        const int c0 = colbase + it * BN;

        float acc[2][4][4];
#pragma unroll
        for (int mi = 0; mi < 2; mi++)
#pragma unroll
            for (int j = 0; j < 4; j++)
#pragma unroll
                for (int r4 = 0; r4 < 4; r4++) acc[mi][j][r4] = 0.f;

#pragma unroll
        for (int kk = 0; kk < DD / 32; kk++) {   // 8 k-steps of k32 (32 B each)
            uint32_t a0[4], a1[4], bb0[4], bb1[4];
            ldsm4(a0[0], a0[1], a0[2], a0[3], As_u + a_off0 + kk * 32);
            ldsm4(a1[0], a1[1], a1[2], a1[3], As_u + a_off1 + kk * 32);
            ldsm4(bb0[0], bb0[1], bb0[2], bb0[3], Bc + b_off0 + kk * 32);
            ldsm4(bb1[0], bb1[1], bb1[2], bb1[3], Bc + b_off1 + kk * 32);
            mma16832(acc[0][0], a0, bb0[0], bb0[1]);
            mma16832(acc[0][1], a0, bb0[2], bb0[3]);
            mma16832(acc[0][2], a0, bb1[0], bb1[1]);
            mma16832(acc[0][3], a0, bb1[2], bb1[3]);
            mma16832(acc[1][0], a1, bb0[0], bb0[1]);
            mma16832(acc[1][1], a1, bb0[2], bb0[3]);
            mma16832(acc[1][2], a1, bb1[0], bb1[1]);
            mma16832(acc[1][3], a1, bb1[2], bb1[3]);
        }

        // --- register-only epilogue ---
#pragma unroll
        for (int mi = 0; mi < 2; mi++) {
            const int R1 = row0 + warp_m * 32 + mi * 16 + gid;
            const int R2 = R1 + 8;
            const int T1 = R1 ^ HALF_N, T2 = R2 ^ HALF_N;
#pragma unroll
            for (int j = 0; j < 4; j++) {
                const int C0 = c0 + warp_n * 32 + j * 8 + qd * 2;
                const int C1 = C0 + 1;
                const float s00 = acc[mi][j][0] * 2.f, s01 = acc[mi][j][1] * 2.f;
                const float s10 = acc[mi][j][2] * 2.f, s11 = acc[mi][j][3] * 2.f;
                if (C0 != R1) p[mi][0] += __expf(s00 - 2.f);
                if (C1 != R1) p[mi][0] += __expf(s01 - 2.f);
                if (C0 != R2) p[mi][1] += __expf(s10 - 2.f);
                if (C1 != R2) p[mi][1] += __expf(s11 - 2.f);
                tv[mi][0] += (C0 == T1) ? s00 : 0.f;
                tv[mi][0] += (C1 == T1) ? s01 : 0.f;
                tv[mi][1] += (C0 == T2) ? s10 : 0.f;
                tv[mi][1] += (C1 == T2) ? s11 : 0.f;
            }
        }
    }

    cp_wait<0>();

    // --- reduce quad lanes, then 4 warp_n warps via smem ---
#pragma unroll
    for (int mi = 0; mi < 2; mi++)
#pragma unroll
        for (int h = 0; h < 2; h++) {
            float pp = p[mi][h], tt = tv[mi][h];
            pp += __shfl_xor_sync(0xffffffffu, pp, 1);
            pp += __shfl_xor_sync(0xffffffffu, pp, 2);
            tt += __shfl_xor_sync(0xffffffffu, tt, 1);
            tt += __shfl_xor_sync(0xffffffffu, tt, 2);
            p[mi][h] = pp; tv[mi][h] = tt;
        }

    __syncthreads();
    float* redp = (float*)smem;            // [128][4]
    float* redt = redp + BM * 4;
    if (qd == 0) {
#pragma unroll
        for (int mi = 0; mi < 2; mi++)
#pragma unroll
            for (int h = 0; h < 2; h++) {
                int rl = warp_m * 32 + mi * 16 + h * 8 + gid;
                redp[rl * 4 + warp_n] = p[mi][h];
                redt[rl * 4 + warp_n] = tv[mi][h];
            }
    }
    __syncthreads();
    if (tid < BM) {
        float pp = redp[tid * 4] + redp[tid * 4 + 1] + redp[tid * 4 + 2] + redp[tid * 4 + 3];
        float tt = redt[tid * 4] + redt[tid * 4 + 1] + redt[tid * 4 + 2] + redt[tid * 4 + 3];
        g_p[ch * TWO_N + row0 + tid] = pp;
        g_t[ch * TWO_N + row0 + tid] = tt;
    }
}

// ---------------- phase 3: combine halves, log, mean ----------------
__global__ void reduce_kernel(float* __restrict__ out) {
    int t = threadIdx.x;
    float s = 0.f;
    for (int i = t; i < TWO_N; i += 256) {
        float pp = g_p[i] + g_p[TWO_N + i];
        float tt = g_t[i] + g_t[TWO_N + i];
        s += 2.0f + logf(pp) - tt;
    }
#pragma unroll
    for (int o = 16; o > 0; o >>= 1) s += __shfl_xor_sync(0xffffffffu, s, o);
    __shared__ float ws[8];
    if ((t & 31) == 0) ws[t >> 5] = s;
    __syncthreads();
    if (t == 0) {
        float tot = 0.f;
#pragma unroll
        for (int j = 0; j < 8; j++) tot += ws[j];
        out[0] = tot * (1.0f / (float)TWO_N);
    }
}

extern "C" void kernel_launch(void* const* d_in, const int* in_sizes, int n_in,
                              void* d_out, int out_size) {
    const float* z1 = (const float*)d_in[0];
    const float* z2 = (const float*)d_in[1];
    float* out = (float*)d_out;
    (void)in_sizes; (void)n_in; (void)out_size;

    cudaFuncSetAttribute(ntxent_mma_kernel,
                         cudaFuncAttributeMaxDynamicSharedMemorySize, SMEM_BYTES);

    normalize_kernel<<<TWO_N / 8, 256>>>(z1, z2);
    ntxent_mma_kernel<<<(TWO_N / BM) * 2, NTHREADS, SMEM_BYTES>>>();
    reduce_kernel<<<1, 256>>>(out);
}

// round 14
// speedup vs baseline: 1.5361x; 1.5361x over previous
#include <cuda_runtime.h>
#include <cuda_bf16.h>
#include <cuda_fp8.h>
#include <cstdint>

// NT-Xent loss, N=4096, D=256, T=0.5 — FP8 mma.sync, SYMMETRIC (upper-triangle) sweep.
// sim is exactly symmetric => compute only band tiles (bi<=bj) over 64 bands of 128:
// 2080 tiles instead of 4096. Off-diag tiles contribute row-sums to band bi and
// column-sums (transpose) to band bj. Deterministic: g_part[row][slot=opposing band],
// each slot written by exactly one tile. lse = 2 + log(sum exp(sim-2)) : stable.

#define TWO_N 8192
#define HALF_N 4096
#define DD 256
#define BM 128
#define NBANDS 64          // TWO_N / BM
#define NTILES 2080        // 64*65/2
#define GRID 148
#define SBB 272            // smem row stride bytes (256 + 16 pad)
#define NTHREADS 512

__device__ uint8_t g_zn8[TWO_N * DD];          // normalized rows, e4m3 (2 MB, L2-resident)
__device__ float g_part[(size_t)TWO_N * NBANDS]; // [row][opposing band] exp-sum partials
__device__ float g_tv[TWO_N];                  // target sim per row (each written once)
__device__ float g_rowloss[TWO_N];

#define TILE_BYTES (BM * SBB)                  // 34816
#define RED_OFF (4 * TILE_BYTES)               // rp[128*4], cp[128*4] floats after buffers
#define SMEM_BYTES (RED_OFF + 4096)            // 143360

// ---------------- PTX helpers ----------------
__device__ __forceinline__ void cp16(uint32_t dst, const void* src) {
    asm volatile("cp.async.cg.shared.global [%0], [%1], 16;" :: "r"(dst), "l"(src));
}
__device__ __forceinline__ void cp_commit() { asm volatile("cp.async.commit_group;"); }
template <int N> __device__ __forceinline__ void cp_wait() {
    asm volatile("cp.async.wait_group %0;" :: "n"(N));
}
__device__ __forceinline__ void ldsm4(uint32_t& x0, uint32_t& x1, uint32_t& x2, uint32_t& x3,
                                      uint32_t addr) {
    asm volatile("ldmatrix.sync.aligned.m8n8.x4.shared.b16 {%0,%1,%2,%3}, [%4];"
                 : "=r"(x0), "=r"(x1), "=r"(x2), "=r"(x3) : "r"(addr));
}
__device__ __forceinline__ void mma16832(float* c, const uint32_t* a, uint32_t b0, uint32_t b1) {
    asm volatile("mma.sync.aligned.m16n8k32.row.col.f32.e4m3.e4m3.f32 "
                 "{%0,%1,%2,%3}, {%4,%5,%6,%7}, {%8,%9}, {%0,%1,%2,%3};"
                 : "+f"(c[0]), "+f"(c[1]), "+f"(c[2]), "+f"(c[3])
                 : "r"(a[0]), "r"(a[1]), "r"(a[2]), "r"(a[3]), "r"(b0), "r"(b1));
}

__device__ __forceinline__ void decode_tile(int t, int& bi, int& bj) {
    int b = 0;
    while (t >= NBANDS - b) { t -= NBANDS - b; b++; }
    bi = b;
    bj = b + t;
}

// ---------------- phase 1: normalize fp32 -> e4m3 (warp per row) ----------------
__global__ void normalize_kernel(const float* __restrict__ z1,
                                 const float* __restrict__ z2) {
    int w = threadIdx.x >> 5, lane = threadIdx.x & 31;
    int row = blockIdx.x * 8 + w;
    const float* src = (row < HALF_N) ? (z1 + (size_t)row * DD)
                                      : (z2 + (size_t)(row - HALF_N) * DD);
    float4 f0 = *(const float4*)(src + lane * 8);
    float4 f1 = *(const float4*)(src + lane * 8 + 4);
    float ss = f0.x * f0.x + f0.y * f0.y + f0.z * f0.z + f0.w * f0.w
             + f1.x * f1.x + f1.y * f1.y + f1.z * f1.z + f1.w * f1.w;
#pragma unroll
    for (int o = 16; o > 0; o >>= 1) ss += __shfl_xor_sync(0xffffffffu, ss, o);
    float inv = 1.0f / fmaxf(sqrtf(ss), 1e-8f);

    uint8_t ob[8];
    ob[0] = (uint8_t)__nv_cvt_float_to_fp8(f0.x * inv, __NV_SATFINITE, __NV_E4M3);
    ob[1] = (uint8_t)__nv_cvt_float_to_fp8(f0.y * inv, __NV_SATFINITE, __NV_E4M3);
    ob[2] = (uint8_t)__nv_cvt_float_to_fp8(f0.z * inv, __NV_SATFINITE, __NV_E4M3);
    ob[3] = (uint8_t)__nv_cvt_float_to_fp8(f0.w * inv, __NV_SATFINITE, __NV_E4M3);
    ob[4] = (uint8_t)__nv_cvt_float_to_fp8(f1.x * inv, __NV_SATFINITE, __NV_E4M3);
    ob[5] = (uint8_t)__nv_cvt_float_to_fp8(f1.y * inv, __NV_SATFINITE, __NV_E4M3);
    ob[6] = (uint8_t)__nv_cvt_float_to_fp8(f1.z * inv, __NV_SATFINITE, __NV_E4M3);
    ob[7] = (uint8_t)__nv_cvt_float_to_fp8(f1.w * inv, __NV_SATFINITE, __NV_E4M3);
    *(uint2*)(g_zn8 + (size_t)row * DD + lane * 8) = *(const uint2*)ob;
}

// ---------------- phase 2: triangular FP8 MMA sweep ----------------
__global__ __launch_bounds__(NTHREADS, 1) void ntxent_mma_kernel() {
    extern __shared__ __align__(16) char smem[];

    const int tid = threadIdx.x;
    const int lane = tid & 31, wid = tid >> 5;
    const int warp_m = wid & 3;
    const int warp_n = wid >> 2;

    const uint32_t S = (uint32_t)__cvta_generic_to_shared(smem);
    const uint32_t bufA[2] = { S,                  S + 2 * TILE_BYTES };
    const uint32_t bufB[2] = { S + TILE_BYTES,     S + 3 * TILE_BYTES };
    float* rp = (float*)(smem + RED_OFF);          // [128][4]
    float* cpd = rp + BM * 4;                      // [128][4]

    const int cnt = 14 + ((int)blockIdx.x < (NTILES - 14 * GRID) ? 1 : 0);

    // ldmatrix per-lane addressing (byte-identical to validated R13 layout)
    const int g = lane >> 3, rr = lane & 7;
    const uint32_t a_off0 = (uint32_t)((warp_m * 32 + (lane & 15)) * SBB + (lane >> 4) * 16);
    const uint32_t a_off1 = a_off0 + 16 * SBB;
    const uint32_t b_off0 = (uint32_t)((warp_n * 32 + (g >> 1) * 8 + rr) * SBB + (g & 1) * 16);
    const uint32_t b_off1 = b_off0 + 16 * SBB;
    const int gid = lane >> 2, qd = lane & 3;

    // prologue: tile 0
    int bi, bj;
    decode_tile(blockIdx.x, bi, bj);
    {
        const uint8_t* sa = g_zn8 + (size_t)bi * BM * DD;
        const uint8_t* sb = g_zn8 + (size_t)bj * BM * DD;
#pragma unroll
        for (int q = 0; q < 4; q++) {
            int c = tid + q * NTHREADS;
            int row = c >> 4, off = c & 15;
            cp16(bufA[0] + row * SBB + off * 16, sa + row * DD + off * 16);
            cp16(bufB[0] + row * SBB + off * 16, sb + row * DD + off * 16);
        }
    }
    cp_commit();

    for (int it = 0; it < cnt; it++) {
        __syncthreads();   // everyone finished reading buf[(it-1)&1] and red arrays

        int nbi = bi, nbj = bj;
        if (it + 1 < cnt) {
            decode_tile((int)blockIdx.x + (it + 1) * GRID, nbi, nbj);
            const uint8_t* sa = g_zn8 + (size_t)nbi * BM * DD;
            const uint8_t* sb = g_zn8 + (size_t)nbj * BM * DD;
            const uint32_t da = bufA[(it + 1) & 1], db = bufB[(it + 1) & 1];
#pragma unroll
            for (int q = 0; q < 4; q++) {
                int c = tid + q * NTHREADS;
                int row = c >> 4, off = c & 15;
                cp16(da + row * SBB + off * 16, sa + row * DD + off * 16);
                cp16(db + row * SBB + off * 16, sb + row * DD + off * 16);
            }
        }
        cp_commit();
        cp_wait<1>();      // tile it resident (tile it+1 pending)
        __syncthreads();

        const uint32_t Au = bufA[it & 1], Bc = bufB[it & 1];

        float acc[2][4][4];
#pragma unroll
        for (int mi = 0; mi < 2; mi++)
#pragma unroll
            for (int j = 0; j < 4; j++)
#pragma unroll
                for (int r4 = 0; r4 < 4; r4++) acc[mi][j][r4] = 0.f;

#pragma unroll
        for (int kk = 0; kk < DD / 32; kk++) {
            uint32_t a0[4], a1[4], bb0[4], bb1[4];
            ldsm4(a0[0], a0[1], a0[2], a0[3], Au + a_off0 + kk * 32);
            ldsm4(a1[0], a1[1], a1[2], a1[3], Au + a_off1 + kk * 32);
            ldsm4(bb0[0], bb0[1], bb0[2], bb0[3], Bc + b_off0 + kk * 32);
            ldsm4(bb1[0], bb1[1], bb1[2], bb1[3], Bc + b_off1 + kk * 32);
            mma16832(acc[0][0], a0, bb0[0], bb0[1]);
            mma16832(acc[0][1], a0, bb0[2], bb0[3]);
            mma16832(acc[0][2], a0, bb1[0], bb1[1]);
            mma16832(acc[0][3], a0, bb1[2], bb1[3]);
            mma16832(acc[1][0], a1, bb0[0], bb0[1]);
            mma16832(acc[1][1], a1, bb0[2], bb0[3]);
            mma16832(acc[1][2], a1, bb1[0], bb1[1]);
            mma16832(acc[1][3], a1, bb1[2], bb1[3]);
        }

        // --- epilogue: exps + row partials (band bi) + col partials (band bj) ---
        const bool diag = (bi == bj);
        const bool tgt_tile = (bj == (bi ^ 32));   // band of i^4096 is band^32
        const int rowg0 = bi * BM, colg0 = bj * BM;

        float rs[2][2] = {{0.f, 0.f}, {0.f, 0.f}};
        float cs[4][2] = {{0.f, 0.f}, {0.f, 0.f}, {0.f, 0.f}, {0.f, 0.f}};

#pragma unroll
        for (int mi = 0; mi < 2; mi++) {
            const int R1 = rowg0 + warp_m * 32 + mi * 16 + gid;
            const int R2 = R1 + 8;
#pragma unroll
            for (int j = 0; j < 4; j++) {
                const int C0 = colg0 + warp_n * 32 + j * 8 + qd * 2;
                const int C1 = C0 + 1;
                const float s00 = acc[mi][j][0] * 2.f, s01 = acc[mi][j][1] * 2.f;
                const float s10 = acc[mi][j][2] * 2.f, s11 = acc[mi][j][3] * 2.f;
                float e00 = __expf(s00 - 2.f), e01 = __expf(s01 - 2.f);
                float e10 = __expf(s10 - 2.f), e11 = __expf(s11 - 2.f);
                if (diag) {
                    if (C0 == R1) e00 = 0.f;
                    if (C1 == R1) e01 = 0.f;
                    if (C0 == R2) e10 = 0.f;
                    if (C1 == R2) e11 = 0.f;
                }
                if (tgt_tile) {
                    if (C0 == (R1 ^ HALF_N)) { g_tv[R1] = s00; g_tv[C0] = s00; }
                    if (C1 == (R1 ^ HALF_N)) { g_tv[R1] = s01; g_tv[C1] = s01; }
                    if (C0 == (R2 ^ HALF_N)) { g_tv[R2] = s10; g_tv[C0] = s10; }
                    if (C1 == (R2 ^ HALF_N)) { g_tv[R2] = s11; g_tv[C1] = s11; }
                }
                rs[mi][0] += e00 + e01;
                rs[mi][1] += e10 + e11;
                cs[j][0] += e00 + e10;
                cs[j][1] += e01 + e11;
            }
        }

        // row reduce over qd lanes (bits 0,1)
#pragma unroll
        for (int mi = 0; mi < 2; mi++)
#pragma unroll
            for (int h = 0; h < 2; h++) {
                float v = rs[mi][h];
                v += __shfl_xor_sync(0xffffffffu, v, 1);
                v += __shfl_xor_sync(0xffffffffu, v, 2);
                if (qd == 0)
                    rp[(warp_m * 32 + mi * 16 + h * 8 + gid) * 4 + warp_n] = v;
            }
        // col reduce over gid lanes (bits 2,3,4)
#pragma unroll
        for (int j = 0; j < 4; j++)
#pragma unroll
            for (int c = 0; c < 2; c++) {
                float v = cs[j][c];
                v += __shfl_xor_sync(0xffffffffu, v, 4);
                v += __shfl_xor_sync(0xffffffffu, v, 8);
                v += __shfl_xor_sync(0xffffffffu, v, 16);
                if (gid == 0)
                    cpd[(warp_n * 32 + j * 8 + qd * 2 + c) * 4 + warp_m] = v;
            }

        __syncthreads();

        if (tid < BM) {
            float v = rp[tid * 4] + rp[tid * 4 + 1] + rp[tid * 4 + 2] + rp[tid * 4 + 3];
            g_part[(size_t)(rowg0 + tid) * NBANDS + bj] = v;
        } else if (tid < 2 * BM && !diag) {
            int r = tid - BM;
            float v = cpd[r * 4] + cpd[r * 4 + 1] + cpd[r * 4 + 2] + cpd[r * 4 + 3];
            g_part[(size_t)(colg0 + r) * NBANDS + bi] = v;
        }

        bi = nbi; bj = nbj;
    }
    cp_wait<0>();
}

// ---------------- phase 3a: per-row loss ----------------
__global__ void rowloss_kernel() {
    int r = blockIdx.x * 128 + threadIdx.x;
    const float* p = g_part + (size_t)r * NBANDS;
    float s = 0.f;
#pragma unroll
    for (int i = 0; i < NBANDS; i++) s += p[i];
    g_rowloss[r] = 2.0f + logf(s) - g_tv[r];
}

// ---------------- phase 3b: mean ----------------
__global__ void reduce_kernel(float* __restrict__ out) {
    int t = threadIdx.x;
    float s = 0.f;
    for (int i = t; i < TWO_N; i += 256) s += g_rowloss[i];
#pragma unroll
    for (int o = 16; o > 0; o >>= 1) s += __shfl_xor_sync(0xffffffffu, s, o);
    __shared__ float ws[8];
    if ((t & 31) == 0) ws[t >> 5] = s;
    __syncthreads();
    if (t == 0) {
        float tot = 0.f;
#pragma unroll
        for (int j = 0; j < 8; j++) tot += ws[j];
        out[0] = tot * (1.0f / (float)TWO_N);
    }
}

extern "C" void kernel_launch(void* const* d_in, const int* in_sizes, int n_in,
                              void* d_out, int out_size) {
    const float* z1 = (const float*)d_in[0];
    const float* z2 = (const float*)d_in[1];
    float* out = (float*)d_out;
    (void)in_sizes; (void)n_in; (void)out_size;

    cudaFuncSetAttribute(ntxent_mma_kernel,
                         cudaFuncAttributeMaxDynamicSharedMemorySize, SMEM_BYTES);

    normalize_kernel<<<TWO_N / 8, 256>>>(z1, z2);
    ntxent_mma_kernel<<<GRID, NTHREADS, SMEM_BYTES>>>();
    rowloss_kernel<<<TWO_N / 128, 128>>>();
    reduce_kernel<<<1, 256>>>(out);
}

// round 16
// speedup vs baseline: 1.7192x; 1.1192x over previous
#include <cuda_runtime.h>
#include <cuda_bf16.h>
#include <cuda_fp8.h>
#include <cstdint>

// NT-Xent loss, N=4096, D=256, T=0.5 — FP8 mma.sync, symmetric (upper-triangle) sweep.
// 2080 band tiles (64 bands x 128 rows, bi<=bj); off-diag tiles feed row sums (band bi)
// and transposed column sums (band bj). Deterministic scatter: g_part[row][opposing band].
// lse = 2 + log(sum exp(sim-2)) : exact-stable since sim in [-2,2].
// This round: 1 barrier/tile (deferred partial accumulation, 3-deep buffers) and a
// fused rowloss+mean finalize kernel (last-block pattern).

#define TWO_N 8192
#define HALF_N 4096
#define DD 256
#define BM 128
#define NBANDS 64
#define NTILES 2080
#define GRID 148
#define SBB 272               // smem row stride bytes (256 + 16 pad)
#define NTHREADS 512

__device__ uint8_t g_zn8[TWO_N * DD];            // normalized rows, e4m3 (2 MB, L2-resident)
__device__ float g_part[(size_t)TWO_N * NBANDS]; // [row][opposing band] exp-sum partials
__device__ float g_tv[TWO_N];                    // target sim per row (written once each)
__device__ float g_bsum[32];
__device__ int g_done = 0;

#define TILE_BYTES (BM * SBB)                    // 34816
#define RED_OFF (6 * TILE_BYTES)                 // after 3 (A,B) buffer pairs
#define SMEM_BYTES (RED_OFF + 8192)              // 217088 <= 227KB

// ---------------- PTX helpers ----------------
__device__ __forceinline__ void cp16(uint32_t dst, const void* src) {
    asm volatile("cp.async.cg.shared.global [%0], [%1], 16;" :: "r"(dst), "l"(src));
}
__device__ __forceinline__ void cp_commit() { asm volatile("cp.async.commit_group;"); }
template <int N> __device__ __forceinline__ void cp_wait() {
    asm volatile("cp.async.wait_group %0;" :: "n"(N));
}
__device__ __forceinline__ void ldsm4(uint32_t& x0, uint32_t& x1, uint32_t& x2, uint32_t& x3,
                                      uint32_t addr) {
    asm volatile("ldmatrix.sync.aligned.m8n8.x4.shared.b16 {%0,%1,%2,%3}, [%4];"
                 : "=r"(x0), "=r"(x1), "=r"(x2), "=r"(x3) : "r"(addr));
}
__device__ __forceinline__ void mma16832(float* c, const uint32_t* a, uint32_t b0, uint32_t b1) {
    asm volatile("mma.sync.aligned.m16n8k32.row.col.f32.e4m3.e4m3.f32 "
                 "{%0,%1,%2,%3}, {%4,%5,%6,%7}, {%8,%9}, {%0,%1,%2,%3};"
                 : "+f"(c[0]), "+f"(c[1]), "+f"(c[2]), "+f"(c[3])
                 : "r"(a[0]), "r"(a[1]), "r"(a[2]), "r"(a[3]), "r"(b0), "r"(b1));
}

__device__ __forceinline__ void decode_tile(int t, int& bi, int& bj) {
    int b = 0;
    while (t >= NBANDS - b) { t -= NBANDS - b; b++; }
    bi = b;
    bj = b + t;
}

// ---------------- phase 1: normalize fp32 -> e4m3 (warp per row) ----------------
__global__ void normalize_kernel(const float* __restrict__ z1,
                                 const float* __restrict__ z2) {
    int w = threadIdx.x >> 5, lane = threadIdx.x & 31;
    int row = blockIdx.x * 8 + w;
    const float* src = (row < HALF_N) ? (z1 + (size_t)row * DD)
                                      : (z2 + (size_t)(row - HALF_N) * DD);
    float4 f0 = *(const float4*)(src + lane * 8);
    float4 f1 = *(const float4*)(src + lane * 8 + 4);
    float ss = f0.x * f0.x + f0.y * f0.y + f0.z * f0.z + f0.w * f0.w
             + f1.x * f1.x + f1.y * f1.y + f1.z * f1.z + f1.w * f1.w;
#pragma unroll
    for (int o = 16; o > 0; o >>= 1) ss += __shfl_xor_sync(0xffffffffu, ss, o);
    float inv = 1.0f / fmaxf(sqrtf(ss), 1e-8f);

    uint8_t ob[8];
    ob[0] = (uint8_t)__nv_cvt_float_to_fp8(f0.x * inv, __NV_SATFINITE, __NV_E4M3);
    ob[1] = (uint8_t)__nv_cvt_float_to_fp8(f0.y * inv, __NV_SATFINITE, __NV_E4M3);
    ob[2] = (uint8_t)__nv_cvt_float_to_fp8(f0.z * inv, __NV_SATFINITE, __NV_E4M3);
    ob[3] = (uint8_t)__nv_cvt_float_to_fp8(f0.w * inv, __NV_SATFINITE, __NV_E4M3);
    ob[4] = (uint8_t)__nv_cvt_float_to_fp8(f1.x * inv, __NV_SATFINITE, __NV_E4M3);
    ob[5] = (uint8_t)__nv_cvt_float_to_fp8(f1.y * inv, __NV_SATFINITE, __NV_E4M3);
    ob[6] = (uint8_t)__nv_cvt_float_to_fp8(f1.z * inv, __NV_SATFINITE, __NV_E4M3);
    ob[7] = (uint8_t)__nv_cvt_float_to_fp8(f1.w * inv, __NV_SATFINITE, __NV_E4M3);
    *(uint2*)(g_zn8 + (size_t)row * DD + lane * 8) = *(const uint2*)ob;
}

// ---------------- phase 2: triangular FP8 MMA sweep, 1 barrier/tile ----------------
__global__ __launch_bounds__(NTHREADS, 1) void ntxent_mma_kernel() {
    extern __shared__ __align__(16) char smem[];

    const int tid = threadIdx.x;
    const int lane = tid & 31, wid = tid >> 5;
    const int warp_m = wid & 3;
    const int warp_n = wid >> 2;

    const uint32_t S = (uint32_t)__cvta_generic_to_shared(smem);
    // buffer pair k: A at 2k, B at 2k+1
    float* redbase = (float*)(smem + RED_OFF);   // rp[2][128*4], cpd[2][128*4]

    const int bid = (int)blockIdx.x;
    const int cnt = 14 + (bid < (NTILES - 14 * GRID) ? 1 : 0);

    // ldmatrix per-lane addressing (validated layout)
    const int g = lane >> 3, rr = lane & 7;
    const uint32_t a_off0 = (uint32_t)((warp_m * 32 + (lane & 15)) * SBB + (lane >> 4) * 16);
    const uint32_t a_off1 = a_off0 + 16 * SBB;
    const uint32_t b_off0 = (uint32_t)((warp_n * 32 + (g >> 1) * 8 + rr) * SBB + (g & 1) * 16);
    const uint32_t b_off1 = b_off0 + 16 * SBB;
    const int gid = lane >> 2, qd = lane & 3;

    // rolling tile indices: (bi0,bj0)=tile it, (bi1,bj1)=tile it+1
    int bi0, bj0, bi1 = 0, bj1 = 0;
    decode_tile(bid, bi0, bj0);
    if (cnt > 1) decode_tile(bid + GRID, bi1, bj1);

    // prologue: tile0 -> pair0, tile1 -> pair1 (separate groups)
    {
        const uint8_t* sa = g_zn8 + (size_t)bi0 * BM * DD;
        const uint8_t* sb = g_zn8 + (size_t)bj0 * BM * DD;
#pragma unroll
        for (int q = 0; q < 4; q++) {
            int c = tid + q * NTHREADS;
            int row = c >> 4, off = c & 15;
            cp16(S + row * SBB + off * 16, sa + row * DD + off * 16);
            cp16(S + TILE_BYTES + row * SBB + off * 16, sb + row * DD + off * 16);
        }
    }
    cp_commit();
    if (cnt > 1) {
        const uint8_t* sa = g_zn8 + (size_t)bi1 * BM * DD;
        const uint8_t* sb = g_zn8 + (size_t)bj1 * BM * DD;
#pragma unroll
        for (int q = 0; q < 4; q++) {
            int c = tid + q * NTHREADS;
            int row = c >> 4, off = c & 15;
            cp16(S + 2 * TILE_BYTES + row * SBB + off * 16, sa + row * DD + off * 16);
            cp16(S + 3 * TILE_BYTES + row * SBB + off * 16, sb + row * DD + off * 16);
        }
    }
    cp_commit();

    int pbi = 0, pbj = 0;    // previous tile (for deferred accumulation)

    for (int it = 0; it < cnt; it++) {
        cp_wait<1>();        // tile it fully resident (it+1 may be pending)
        __syncthreads();     // all chunks visible; all reads of pair[(it+2)%3] (iter it-1) done;
                             // red[(it-1)&1] writes visible

        // --- deferred: accumulate tile it-1 partials to gmem ---
        if (it > 0) {
            const float* rpp = redbase + ((it - 1) & 1) * (BM * 4);
            const float* cpp = redbase + 2 * (BM * 4) + ((it - 1) & 1) * (BM * 4);
            if (tid < BM) {
                float v = rpp[tid * 4] + rpp[tid * 4 + 1] + rpp[tid * 4 + 2] + rpp[tid * 4 + 3];
                g_part[(size_t)(pbi * BM + tid) * NBANDS + pbj] = v;
            } else if (tid < 2 * BM && pbi != pbj) {
                int r = tid - BM;
                float v = cpp[r * 4] + cpp[r * 4 + 1] + cpp[r * 4 + 2] + cpp[r * 4 + 3];
                g_part[(size_t)(pbj * BM + r) * NBANDS + pbi] = v;
            }
        }

        // --- prefetch tile it+2 into pair (it+2)%3 ---
        int bi2 = 0, bj2 = 0;
        if (it + 2 < cnt) {
            decode_tile(bid + (it + 2) * GRID, bi2, bj2);
            const uint8_t* sa = g_zn8 + (size_t)bi2 * BM * DD;
            const uint8_t* sb = g_zn8 + (size_t)bj2 * BM * DD;
            const uint32_t da = S + ((it + 2) % 3) * 2 * TILE_BYTES;
            const uint32_t db = da + TILE_BYTES;
#pragma unroll
            for (int q = 0; q < 4; q++) {
                int c = tid + q * NTHREADS;
                int row = c >> 4, off = c & 15;
                cp16(da + row * SBB + off * 16, sa + row * DD + off * 16);
                cp16(db + row * SBB + off * 16, sb + row * DD + off * 16);
            }
        }
        cp_commit();         // commit even when empty: keeps group accounting uniform

        const uint32_t Au = S + (it % 3) * 2 * TILE_BYTES;
        const uint32_t Bc = Au + TILE_BYTES;

        float acc[2][4][4];
#pragma unroll
        for (int mi = 0; mi < 2; mi++)
#pragma unroll
            for (int j = 0; j < 4; j++)
#pragma unroll
                for (int r4 = 0; r4 < 4; r4++) acc[mi][j][r4] = 0.f;

#pragma unroll
        for (int kk = 0; kk < DD / 32; kk++) {
            uint32_t a0[4], a1[4], bb0[4], bb1[4];
            ldsm4(a0[0], a0[1], a0[2], a0[3], Au + a_off0 + kk * 32);
            ldsm4(a1[0], a1[1], a1[2], a1[3], Au + a_off1 + kk * 32);
            ldsm4(bb0[0], bb0[1], bb0[2], bb0[3], Bc + b_off0 + kk * 32);
            ldsm4(bb1[0], bb1[1], bb1[2], bb1[3], Bc + b_off1 + kk * 32);
            mma16832(acc[0][0], a0, bb0[0], bb0[1]);
            mma16832(acc[0][1], a0, bb0[2], bb0[3]);
            mma16832(acc[0][2], a0, bb1[0], bb1[1]);
            mma16832(acc[0][3], a0, bb1[2], bb1[3]);
            mma16832(acc[1][0], a1, bb0[0], bb0[1]);
            mma16832(acc[1][1], a1, bb0[2], bb0[3]);
            mma16832(acc[1][2], a1, bb1[0], bb1[1]);
            mma16832(acc[1][3], a1, bb1[2], bb1[3]);
        }

        // --- epilogue: exps + per-warp partial reductions into red[it&1] ---
        const bool diag = (bi0 == bj0);
        const bool tgt_tile = (bj0 == (bi0 ^ 32));
        const int rowg0 = bi0 * BM, colg0 = bj0 * BM;

        float rs[2][2] = {{0.f, 0.f}, {0.f, 0.f}};
        float cs[4][2] = {{0.f, 0.f}, {0.f, 0.f}, {0.f, 0.f}, {0.f, 0.f}};

#pragma unroll
        for (int mi = 0; mi < 2; mi++) {
            const int R1 = rowg0 + warp_m * 32 + mi * 16 + gid;
            const int R2 = R1 + 8;
#pragma unroll
            for (int j = 0; j < 4; j++) {
                const int C0 = colg0 + warp_n * 32 + j * 8 + qd * 2;
                const int C1 = C0 + 1;
                const float s00 = acc[mi][j][0] * 2.f, s01 = acc[mi][j][1] * 2.f;
                const float s10 = acc[mi][j][2] * 2.f, s11 = acc[mi][j][3] * 2.f;
                float e00 = __expf(s00 - 2.f), e01 = __expf(s01 - 2.f);
                float e10 = __expf(s10 - 2.f), e11 = __expf(s11 - 2.f);
                if (diag) {
                    if (C0 == R1) e00 = 0.f;
                    if (C1 == R1) e01 = 0.f;
                    if (C0 == R2) e10 = 0.f;
                    if (C1 == R2) e11 = 0.f;
                }
                if (tgt_tile) {
                    if (C0 == (R1 ^ HALF_N)) { g_tv[R1] = s00; g_tv[C0] = s00; }
                    if (C1 == (R1 ^ HALF_N)) { g_tv[R1] = s01; g_tv[C1] = s01; }
                    if (C0 == (R2 ^ HALF_N)) { g_tv[R2] = s10; g_tv[C0] = s10; }
                    if (C1 == (R2 ^ HALF_N)) { g_tv[R2] = s11; g_tv[C1] = s11; }
                }
                rs[mi][0] += e00 + e01;
                rs[mi][1] += e10 + e11;
                cs[j][0] += e00 + e10;
                cs[j][1] += e01 + e11;
            }
        }

        float* rpw = redbase + (it & 1) * (BM * 4);
        float* cpw = redbase + 2 * (BM * 4) + (it & 1) * (BM * 4);
        // row reduce over qd lanes (bits 0,1)
#pragma unroll
        for (int mi = 0; mi < 2; mi++)
#pragma unroll
            for (int h = 0; h < 2; h++) {
                float v = rs[mi][h];
                v += __shfl_xor_sync(0xffffffffu, v, 1);
                v += __shfl_xor_sync(0xffffffffu, v, 2);
                if (qd == 0)
                    rpw[(warp_m * 32 + mi * 16 + h * 8 + gid) * 4 + warp_n] = v;
            }
        // col reduce over gid lanes (bits 2,3,4)
#pragma unroll
        for (int j = 0; j < 4; j++)
#pragma unroll
            for (int c = 0; c < 2; c++) {
                float v = cs[j][c];
                v += __shfl_xor_sync(0xffffffffu, v, 4);
                v += __shfl_xor_sync(0xffffffffu, v, 8);
                v += __shfl_xor_sync(0xffffffffu, v, 16);
                if (gid == 0)
                    cpw[(warp_n * 32 + j * 8 + qd * 2 + c) * 4 + warp_m] = v;
            }

        pbi = bi0; pbj = bj0;
        bi0 = bi1; bj0 = bj1;
        bi1 = bi2; bj1 = bj2;
    }

    // flush last tile's partials
    cp_wait<0>();
    __syncthreads();
    {
        const float* rpp = redbase + ((cnt - 1) & 1) * (BM * 4);
        const float* cpp = redbase + 2 * (BM * 4) + ((cnt - 1) & 1) * (BM * 4);
        if (tid < BM) {
            float v = rpp[tid * 4] + rpp[tid * 4 + 1] + rpp[tid * 4 + 2] + rpp[tid * 4 + 3];
            g_part[(size_t)(pbi * BM + tid) * NBANDS + pbj] = v;
        } else if (tid < 2 * BM && pbi != pbj) {
            int r = tid - BM;
            float v = cpp[r * 4] + cpp[r * 4 + 1] + cpp[r * 4 + 2] + cpp[r * 4 + 3];
            g_part[(size_t)(pbj * BM + r) * NBANDS + pbi] = v;
        }
    }
}

// ---------------- phase 3: fused row-loss + mean (last-block pattern) ----------------
__global__ void finalize_kernel(float* __restrict__ out) {
    int t = threadIdx.x;
    int r = blockIdx.x * 256 + t;          // 32 blocks x 256 threads = 8192 rows
    const float4* p = (const float4*)(g_part + (size_t)r * NBANDS);
    float s = 0.f;
#pragma unroll
    for (int i = 0; i < 16; i++) {
        float4 v = p[i];
        s += v.x + v.y + v.z + v.w;
    }
    float rl = 2.0f + logf(s) - g_tv[r];

#pragma unroll
    for (int o = 16; o > 0; o >>= 1) rl += __shfl_xor_sync(0xffffffffu, rl, o);
    __shared__ float ws[8];
    if ((t & 31) == 0) ws[t >> 5] = rl;
    __syncthreads();
    if (t == 0) {
        float tot = 0.f;
#pragma unroll
        for (int j = 0; j < 8; j++) tot += ws[j];
        g_bsum[blockIdx.x] = tot;
        __threadfence();
        if (atomicAdd(&g_done, 1) == 31) {
            volatile float* vb = g_bsum;
            float t2 = 0.f;
#pragma unroll
            for (int i = 0; i < 32; i++) t2 += vb[i];   // fixed order: deterministic
            out[0] = t2 * (1.0f / (float)TWO_N);
            g_done = 0;                                  // reset for graph replay
        }
    }
}

extern "C" void kernel_launch(void* const* d_in, const int* in_sizes, int n_in,
                              void* d_out, int out_size) {
    const float* z1 = (const float*)d_in[0];
    const float* z2 = (const float*)d_in[1];
    float* out = (float*)d_out;
    (void)in_sizes; (void)n_in; (void)out_size;

    cudaFuncSetAttribute(ntxent_mma_kernel,
                         cudaFuncAttributeMaxDynamicSharedMemorySize, SMEM_BYTES);

    normalize_kernel<<<TWO_N / 8, 256>>>(z1, z2);
    ntxent_mma_kernel<<<GRID, NTHREADS, SMEM_BYTES>>>();
    finalize_kernel<<<32, 256>>>(out);
}